// round 17
// baseline (speedup 1.0000x reference)
#include <cuda_runtime.h>
#include <cuda_bf16.h>
#include <cuda_fp16.h>
#include <cstdint>

#define BATCH 8
#define V1 49152
#define V2 12288
#define V3 3072
#define E1 393216
#define E2 98304
#define E3 24576

// Scratch (device globals; allocation-free rule)
__device__ float g_cheb[125829120];   // fp16 cheb slots live here (reinterpreted)
__device__ float g_out[12582912];     // rotating fp32 buffer b0
__device__ float g_out2[12582912];    // rotating fp32 buffer b1
__device__ float g_part[12582912];    // GEMM phase-1 partial (b2)
// per-level CSR buffers
__device__ int   g_rowPtr1[V1 + 1];  __device__ int g_cursor1[V1 + 1];
__device__ int   g_colS1[E1];        __device__ float g_valS1[E1];
__device__ int   g_orig1[E1];        __device__ int g_bsum1[64];
__device__ int   g_rowPtr2[V2 + 1];  __device__ int g_cursor2[V2 + 1];
__device__ int   g_colS2[E2];        __device__ float g_valS2[E2];
__device__ int   g_orig2[E2];        __device__ int g_bsum2[64];
__device__ int   g_rowPtr3[V3 + 1];  __device__ int g_cursor3[V3 + 1];
__device__ int   g_colS3[E3];        __device__ float g_valS3[E3];
__device__ int   g_orig3[E3];        __device__ int g_bsum3[64];

__device__ __forceinline__ float elu1(float x) { return x > 0.f ? x : expm1f(x); }

// 4 halves <-> 4 floats (uint2 granularity)
__device__ __forceinline__ void h4_unpack(uint2 u, float* o) {
    float2 a = __half22float2(*(__half2*)&u.x);
    float2 b = __half22float2(*(__half2*)&u.y);
    o[0] = a.x; o[1] = a.y; o[2] = b.x; o[3] = b.y;
}
__device__ __forceinline__ uint2 h4_pack(const float* a) {
    __half2 h0 = __floats2half2_rn(a[0], a[1]);
    __half2 h1 = __floats2half2_rn(a[2], a[3]);
    uint2 u;
    u.x = *(uint32_t*)&h0; u.y = *(uint32_t*)&h1;
    return u;
}

// ---------------------------------------------------------------------------
// Utility kernels
// ---------------------------------------------------------------------------
__global__ void k_zero_int(int* p, int n) {
    int i = blockIdx.x * blockDim.x + threadIdx.x;
    if (i < n) p[i] = 0;
}
__global__ void k_transpose_in(const float* __restrict__ x, float* __restrict__ out, int V) {
    int v = blockIdx.x * blockDim.x + threadIdx.x;
    if (v < V) {
#pragma unroll
        for (int b = 0; b < BATCH; b++)
            out[(size_t)v * BATCH + b] = x[(size_t)b * V + v];
    }
}

// ---------------------------------------------------------------------------
// CSR build (deterministic)
// ---------------------------------------------------------------------------
__global__ void k_hist(const int* __restrict__ rows, int* cnt, int E) {
    int e = blockIdx.x * blockDim.x + threadIdx.x;
    if (e < E) atomicAdd(&cnt[rows[e]], 1);
}
__global__ void k_scan_block(const int* __restrict__ cnt, int* __restrict__ outEx,
                             int* __restrict__ bsum, int V) {
    __shared__ int s[1024];
    int tid = threadIdx.x;
    int i = blockIdx.x * 1024 + tid;
    int v = (i < V) ? cnt[i] : 0;
    s[tid] = v;
    __syncthreads();
    for (int off = 1; off < 1024; off <<= 1) {
        int t = 0;
        if (tid >= off) t = s[tid - off];
        __syncthreads();
        s[tid] += t;
        __syncthreads();
    }
    if (i < V) outEx[i] = s[tid] - v;
    if (tid == 1023) bsum[blockIdx.x] = s[1023];
}
__global__ void k_scan_top(int* bsum, int nb) {
    __shared__ int s[64];
    int t = threadIdx.x;
    int v = (t < nb) ? bsum[t] : 0;
    s[t] = v;
    __syncthreads();
    for (int off = 1; off < 64; off <<= 1) {
        int x = (t >= off) ? s[t - off] : 0;
        __syncthreads();
        s[t] += x;
        __syncthreads();
    }
    if (t < nb) bsum[t] = s[t] - v;
}
__global__ void k_scan_add(int* rowPtr, int* cursor, const int* __restrict__ bsum,
                           int V, int E) {
    int i = blockIdx.x * blockDim.x + threadIdx.x;
    if (i < V) {
        int val = rowPtr[i] + bsum[i >> 10];
        rowPtr[i] = val;
        cursor[i] = val;
    }
    if (i == 0) rowPtr[V] = E;
}
__global__ void k_scatter(const int* __restrict__ rows, const int* __restrict__ cols,
                          const float* __restrict__ vals, int* cursor,
                          int* colS, float* valS, int* orig, int E) {
    int e = blockIdx.x * blockDim.x + threadIdx.x;
    if (e < E) {
        int r = rows[e];
        int pos = atomicAdd(&cursor[r], 1);
        colS[pos] = cols[e];
        valS[pos] = vals[e];
        orig[pos] = e;
    }
}
__global__ void k_rowsort(const int* __restrict__ rowPtr, int* colS, float* valS, int* orig, int V) {
    int v = blockIdx.x * blockDim.x + threadIdx.x;
    if (v >= V) return;
    int s = rowPtr[v], e = rowPtr[v + 1];
    for (int i = s + 1; i < e; i++) {
        int ko = orig[i]; int kc = colS[i]; float kv = valS[i];
        int j = i - 1;
        while (j >= s && orig[j] > ko) {
            orig[j + 1] = orig[j]; colS[j + 1] = colS[j]; valS[j + 1] = valS[j];
            j--;
        }
        orig[j + 1] = ko; colS[j + 1] = kc; valS[j + 1] = kv;
    }
}

// ---------------------------------------------------------------------------
// SpMV, fp16 state storage, uint2 per thread (4 features).
// FH = F/4 threads per row -> full warp per row for F>=128 (no divergence).
// PREV: 0 none, 1 fp32, 2 fp16.  IN32: gather source fp32 (pass 1 only).
// 8-edge unroll (MLP 8) with 4/1 tails; per-feature edge order unchanged.
// ---------------------------------------------------------------------------
template <int FH, int ROWS, int PREV, bool IN32>
__global__ void k_spmvh(const int* __restrict__ rowPtr, const int* __restrict__ colS,
                        const float* __restrict__ valS,
                        const void* __restrict__ xin, const void* __restrict__ xprev,
                        uint2* __restrict__ y, int FHS) {
    int f = threadIdx.x;
    int v = blockIdx.x * ROWS + threadIdx.y;
    int s = rowPtr[v], e = rowPtr[v + 1];
    float acc[4];
#pragma unroll
    for (int j = 0; j < 4; j++) acc[j] = 0.f;

    const uint2* xh = (const uint2*)xin;
    const float4* x32 = (const float4*)xin;

    int i = s;
    for (; i + 8 <= e; i += 8) {
        int cc[8]; float ww[8];
#pragma unroll
        for (int t = 0; t < 8; t++) { cc[t] = colS[i + t]; ww[t] = valS[i + t]; }
        if (IN32) {
            float4 a[8];
#pragma unroll
            for (int t = 0; t < 8; t++) a[t] = x32[(size_t)cc[t] * FHS + f];
#pragma unroll
            for (int t = 0; t < 8; t++) {
                acc[0] += ww[t] * a[t].x; acc[1] += ww[t] * a[t].y;
                acc[2] += ww[t] * a[t].z; acc[3] += ww[t] * a[t].w;
            }
        } else {
            uint2 u[8];
#pragma unroll
            for (int t = 0; t < 8; t++) u[t] = xh[(size_t)cc[t] * FHS + f];
#pragma unroll
            for (int t = 0; t < 8; t++) {
                float g[4]; h4_unpack(u[t], g);
#pragma unroll
                for (int j = 0; j < 4; j++) acc[j] += ww[t] * g[j];
            }
        }
    }
    for (; i + 4 <= e; i += 4) {
        int cc[4]; float ww[4];
#pragma unroll
        for (int t = 0; t < 4; t++) { cc[t] = colS[i + t]; ww[t] = valS[i + t]; }
        if (IN32) {
            float4 a[4];
#pragma unroll
            for (int t = 0; t < 4; t++) a[t] = x32[(size_t)cc[t] * FHS + f];
#pragma unroll
            for (int t = 0; t < 4; t++) {
                acc[0] += ww[t] * a[t].x; acc[1] += ww[t] * a[t].y;
                acc[2] += ww[t] * a[t].z; acc[3] += ww[t] * a[t].w;
            }
        } else {
            uint2 u[4];
#pragma unroll
            for (int t = 0; t < 4; t++) u[t] = xh[(size_t)cc[t] * FHS + f];
#pragma unroll
            for (int t = 0; t < 4; t++) {
                float g[4]; h4_unpack(u[t], g);
#pragma unroll
                for (int j = 0; j < 4; j++) acc[j] += ww[t] * g[j];
            }
        }
    }
    for (; i < e; i++) {
        int c = colS[i]; float w = valS[i];
        if (IN32) {
            float4 a = x32[(size_t)c * FHS + f];
            acc[0] += w * a.x; acc[1] += w * a.y; acc[2] += w * a.z; acc[3] += w * a.w;
        } else {
            uint2 u = xh[(size_t)c * FHS + f];
            float g[4]; h4_unpack(u, g);
#pragma unroll
            for (int j = 0; j < 4; j++) acc[j] += w * g[j];
        }
    }

    if (PREV == 1) {
        float4 a = ((const float4*)xprev)[(size_t)v * FHS + f];
        acc[0] = 2.f * acc[0] - a.x; acc[1] = 2.f * acc[1] - a.y;
        acc[2] = 2.f * acc[2] - a.z; acc[3] = 2.f * acc[3] - a.w;
    } else if (PREV == 2) {
        uint2 u = ((const uint2*)xprev)[(size_t)v * FHS + f];
        float g[4]; h4_unpack(u, g);
#pragma unroll
        for (int j = 0; j < 4; j++) acc[j] = 2.f * acc[j] - g[j];
    }
    y[(size_t)v * FHS + f] = h4_pack(acc);
}

// ---------------------------------------------------------------------------
// mma.sync bf16x3 Chebyshev GEMM, two-phase. Slot 0 = fp32 A0; slots 1..9 fp16.
// ---------------------------------------------------------------------------
__device__ __forceinline__ void mma16816(float* d, const uint32_t* a, const uint32_t* b) {
    asm volatile(
        "mma.sync.aligned.m16n8k16.row.col.f32.bf16.bf16.f32 "
        "{%0,%1,%2,%3}, {%4,%5,%6,%7}, {%8,%9}, {%0,%1,%2,%3};\n"
        : "+f"(d[0]), "+f"(d[1]), "+f"(d[2]), "+f"(d[3])
        : "r"(a[0]), "r"(a[1]), "r"(a[2]), "r"(a[3]), "r"(b[0]), "r"(b[1]));
}

__device__ __forceinline__ void split_pack2(float x0, float x1, uint32_t& hi, uint32_t& lo) {
    __nv_bfloat16 h0 = __float2bfloat16_rn(x0);
    __nv_bfloat16 h1 = __float2bfloat16_rn(x1);
    __nv_bfloat16 l0 = __float2bfloat16_rn(x0 - __bfloat162float(h0));
    __nv_bfloat16 l1 = __float2bfloat16_rn(x1 - __bfloat162float(h1));
    __nv_bfloat162 hv(h0, h1), lv(l0, l1);
    hi = *(uint32_t*)&hv;
    lo = *(uint32_t*)&lv;
}

template <int CIN, int COUT, int PHASE>
__global__ __launch_bounds__(256)
void k_gemm_mma(const float* __restrict__ A0, const __half* __restrict__ ArestH,
                size_t slotStride, const float* __restrict__ W,
                const float* __restrict__ bias,
                float* __restrict__ partial, float* __restrict__ out,
                int c0, int c1) {
    constexpr int NT = COUT / 8;

    __shared__ uint32_t Ah[128][17];
    __shared__ uint32_t Al[128][17];
    __shared__ uint32_t Bh[COUT][17];
    __shared__ uint32_t Bl[COUT][17];

    int tid = threadIdx.x;
    int lane = tid & 31;
    int w = tid >> 5;
    int mBase = blockIdx.x * 128;

    float acc[NT][4];
#pragma unroll
    for (int j = 0; j < NT; j++)
#pragma unroll
        for (int q = 0; q < 4; q++) acc[j][q] = 0.f;

    for (int c = c0; c < c1; c++) {
#pragma unroll
        for (int it = 0; it < 4; it++) {
            int idx = it * 256 + tid;
            int r = idx >> 3;
            int q = idx & 7;
            int kk = c * 32 + q * 4;
            int s = kk / CIN;
            int off = kk % CIN;
            uint32_t h0, l0, h1, l1;
            if (s == 0) {
                float4 a = *(const float4*)(A0 + (size_t)(mBase + r) * CIN + off);
                split_pack2(a.x, a.y, h0, l0);
                split_pack2(a.z, a.w, h1, l1);
            } else {
                const __half* src = ArestH + (size_t)(s - 1) * slotStride
                                    + (size_t)(mBase + r) * CIN + off;
                uint2 u = *(const uint2*)src;
                float2 fa = __half22float2(*(__half2*)&u.x);
                float2 fb = __half22float2(*(__half2*)&u.y);
                split_pack2(fa.x, fa.y, h0, l0);
                split_pack2(fb.x, fb.y, h1, l1);
            }
            Ah[r][2 * q] = h0; Ah[r][2 * q + 1] = h1;
            Al[r][2 * q] = l0; Al[r][2 * q + 1] = l1;
        }
        for (int idx = tid; idx < COUT * 16; idx += 256) {
            int k2 = idx / COUT;
            int n = idx % COUT;
            int kk = c * 32 + 2 * k2;
            int s = kk / CIN;
            int off = kk % CIN;
            const float* wp = W + ((size_t)s * CIN + off) * COUT + n;
            float w0 = __ldg(wp);
            float w1 = __ldg(wp + COUT);
            uint32_t h, l;
            split_pack2(w0, w1, h, l);
            Bh[n][k2] = h;
            Bl[n][k2] = l;
        }
        __syncthreads();

#pragma unroll
        for (int ks = 0; ks < 2; ks++) {
            int kq = ks * 8 + (lane & 3);
            int r0 = w * 16 + (lane >> 2);
            uint32_t ah[4], al[4];
            ah[0] = Ah[r0][kq];     ah[1] = Ah[r0 + 8][kq];
            ah[2] = Ah[r0][kq + 4]; ah[3] = Ah[r0 + 8][kq + 4];
            al[0] = Al[r0][kq];     al[1] = Al[r0 + 8][kq];
            al[2] = Al[r0][kq + 4]; al[3] = Al[r0 + 8][kq + 4];
#pragma unroll
            for (int j = 0; j < NT; j++) {
                int n = j * 8 + (lane >> 2);
                uint32_t bh[2] = { Bh[n][kq], Bh[n][kq + 4] };
                uint32_t bl[2] = { Bl[n][kq], Bl[n][kq + 4] };
                mma16816(acc[j], ah, bh);
                mma16816(acc[j], al, bh);
                mma16816(acc[j], ah, bl);
            }
        }
        __syncthreads();
    }

    int r0 = mBase + w * 16 + (lane >> 2);
#pragma unroll
    for (int j = 0; j < NT; j++) {
        int n = j * 8 + 2 * (lane & 3);
        if (PHASE == 0) {
            *(float2*)&partial[(size_t)r0 * COUT + n] = make_float2(acc[j][0], acc[j][1]);
            *(float2*)&partial[(size_t)(r0 + 8) * COUT + n] = make_float2(acc[j][2], acc[j][3]);
        } else {
            float2 q0 = *(const float2*)&partial[(size_t)r0 * COUT + n];
            float2 q1 = *(const float2*)&partial[(size_t)(r0 + 8) * COUT + n];
            float b0 = __ldg(&bias[n]);
            float b1 = __ldg(&bias[n + 1]);
            float2 o0 = make_float2(elu1(acc[j][0] + q0.x + b0), elu1(acc[j][1] + q0.y + b1));
            float2 o1 = make_float2(elu1(acc[j][2] + q1.x + b0), elu1(acc[j][3] + q1.y + b1));
            *(float2*)&out[(size_t)r0 * COUT + n] = o0;
            *(float2*)&out[(size_t)(r0 + 8) * COUT + n] = o1;
        }
    }
}

// CIN=1 special case (level-1 conv1); slots fp16
__global__ void k_gemm_c1(const float* __restrict__ A0, const __half* __restrict__ ArestH,
                          size_t slotStride, const float* __restrict__ W,
                          const float* __restrict__ bias, float* __restrict__ out, int M) {
    __shared__ float Ws[10][32];
    __shared__ float bs[32];
    int tid = threadIdx.y * 32 + threadIdx.x;
    for (int t = tid; t < 320; t += 256) Ws[t / 32][t % 32] = W[t];
    if (tid < 32) bs[tid] = bias[tid];
    __syncthreads();
    int m = blockIdx.x * 8 + threadIdx.y;
    int n = threadIdx.x;
    float acc = A0[m] * Ws[0][n];
#pragma unroll
    for (int k = 1; k < 10; k++)
        acc += __half2float(ArestH[(size_t)(k - 1) * slotStride + m]) * Ws[k][n];
    out[(size_t)m * 32 + n] = elu1(acc + bs[n]);
}

// ---------------------------------------------------------------------------
// Fused skip-write + pooling
// ---------------------------------------------------------------------------
__global__ void k_skip_pool_next4(const float4* __restrict__ in, float4* __restrict__ skip,
                                  float4* __restrict__ pool, int Vin, int C4) {
    int t = blockIdx.x * blockDim.x + threadIdx.x;
    int F4 = BATCH * C4;
    int n = (Vin / 4) * F4;
    if (t >= n) return;
    int v4 = t / F4;
    int f = t - v4 * F4;
    int b = f / C4;
    int c = f - b * C4;
    const float4* bp = in + (size_t)(4 * v4) * F4 + f;
    float4 a0 = bp[0], a1 = bp[F4], a2 = bp[2 * F4], a3 = bp[3 * F4];
    skip[((size_t)b * Vin + 4 * v4 + 0) * C4 + c] = a0;
    skip[((size_t)b * Vin + 4 * v4 + 1) * C4 + c] = a1;
    skip[((size_t)b * Vin + 4 * v4 + 2) * C4 + c] = a2;
    skip[((size_t)b * Vin + 4 * v4 + 3) * C4 + c] = a3;
    float4 o;
    o.x = 0.25f * (a0.x + a1.x + a2.x + a3.x);
    o.y = 0.25f * (a0.y + a1.y + a2.y + a3.y);
    o.z = 0.25f * (a0.z + a1.z + a2.z + a3.z);
    o.w = 0.25f * (a0.w + a1.w + a2.w + a3.w);
    pool[t] = o;
}
__global__ void k_skip_pool_out4(const float4* __restrict__ in, float4* __restrict__ skip,
                                 float4* __restrict__ poolT, int Vin, int C4) {
    int t = blockIdx.x * blockDim.x + threadIdx.x;
    int F4 = BATCH * C4;
    int Vout = Vin / 4;
    int n = Vout * F4;
    if (t >= n) return;
    int v4 = t / F4;
    int f = t - v4 * F4;
    int b = f / C4;
    int c = f - b * C4;
    const float4* bp = in + (size_t)(4 * v4) * F4 + f;
    float4 a0 = bp[0], a1 = bp[F4], a2 = bp[2 * F4], a3 = bp[3 * F4];
    skip[((size_t)b * Vin + 4 * v4 + 0) * C4 + c] = a0;
    skip[((size_t)b * Vin + 4 * v4 + 1) * C4 + c] = a1;
    skip[((size_t)b * Vin + 4 * v4 + 2) * C4 + c] = a2;
    skip[((size_t)b * Vin + 4 * v4 + 3) * C4 + c] = a3;
    float4 o;
    o.x = 0.25f * (a0.x + a1.x + a2.x + a3.x);
    o.y = 0.25f * (a0.y + a1.y + a2.y + a3.y);
    o.z = 0.25f * (a0.z + a1.z + a2.z + a3.z);
    o.w = 0.25f * (a0.w + a1.w + a2.w + a3.w);
    poolT[((size_t)b * Vout + v4) * C4 + c] = o;
}

// ---------------------------------------------------------------------------
// Host orchestration
// ---------------------------------------------------------------------------
static inline int divUp(int a, int b) { return (a + b - 1) / b; }

struct Csr { int* rowPtr; int* cursor; int* colS; float* valS; int* orig; int* bsum; };

struct DevPtrs {
    float* cheb; float* b0; float* b1; float* b2;
    Csr c1, c2, c3;
};
static void get_ptrs(DevPtrs& p) {
    cudaGetSymbolAddress((void**)&p.cheb, g_cheb);
    cudaGetSymbolAddress((void**)&p.b0, g_out);
    cudaGetSymbolAddress((void**)&p.b1, g_out2);
    cudaGetSymbolAddress((void**)&p.b2, g_part);
    cudaGetSymbolAddress((void**)&p.c1.rowPtr, g_rowPtr1);
    cudaGetSymbolAddress((void**)&p.c1.cursor, g_cursor1);
    cudaGetSymbolAddress((void**)&p.c1.colS, g_colS1);
    cudaGetSymbolAddress((void**)&p.c1.valS, g_valS1);
    cudaGetSymbolAddress((void**)&p.c1.orig, g_orig1);
    cudaGetSymbolAddress((void**)&p.c1.bsum, g_bsum1);
    cudaGetSymbolAddress((void**)&p.c2.rowPtr, g_rowPtr2);
    cudaGetSymbolAddress((void**)&p.c2.cursor, g_cursor2);
    cudaGetSymbolAddress((void**)&p.c2.colS, g_colS2);
    cudaGetSymbolAddress((void**)&p.c2.valS, g_valS2);
    cudaGetSymbolAddress((void**)&p.c2.orig, g_orig2);
    cudaGetSymbolAddress((void**)&p.c2.bsum, g_bsum2);
    cudaGetSymbolAddress((void**)&p.c3.rowPtr, g_rowPtr3);
    cudaGetSymbolAddress((void**)&p.c3.cursor, g_cursor3);
    cudaGetSymbolAddress((void**)&p.c3.colS, g_colS3);
    cudaGetSymbolAddress((void**)&p.c3.valS, g_valS3);
    cudaGetSymbolAddress((void**)&p.c3.orig, g_orig3);
    cudaGetSymbolAddress((void**)&p.c3.bsum, g_bsum3);
}

static void build_csr(const Csr& c, const int* rows, const int* cols, const float* vals,
                      int V, int E, cudaStream_t st) {
    k_zero_int<<<divUp(V + 1, 256), 256, 0, st>>>(c.cursor, V + 1);
    k_hist<<<divUp(E, 256), 256, 0, st>>>(rows, c.cursor, E);
    int nb = divUp(V, 1024);
    k_scan_block<<<nb, 1024, 0, st>>>(c.cursor, c.rowPtr, c.bsum, V);
    k_scan_top<<<1, 64, 0, st>>>(c.bsum, nb);
    k_scan_add<<<divUp(V + 1, 256), 256, 0, st>>>(c.rowPtr, c.cursor, c.bsum, V, E);
    k_scatter<<<divUp(E, 256), 256, 0, st>>>(rows, cols, vals, c.cursor, c.colS, c.valS, c.orig, E);
    k_rowsort<<<divUp(V, 256), 256, 0, st>>>(c.rowPtr, c.colS, c.valS, c.orig, V);
}

// fp16 Chebyshev chain, uint2-per-thread geometry. Slots 1..9 at
// (half*)cheb + (k-1)*V*FTOT. foff4 = feature offset / 4 (uint2 & float4 units).
template <int F, int FTOT>
static void spmv_chainh(const DevPtrs& p, const Csr& c, const float* x0base, int V,
                        int foff4, cudaStream_t st, cudaEvent_t evMid = nullptr) {
    constexpr int FH = F / 4;
    constexpr int ROWS = (FH >= 256) ? 1 : (256 / FH);
    constexpr int FHS = FTOT / 4;
    dim3 blk(FH, ROWS);
    size_t S = (size_t)V * FTOT;   // halves per slot
    __half* h = (__half*)p.cheb;
    const void* x0 = (const void*)((const float4*)x0base + foff4);
    auto slot = [&](int k) { return (uint2*)(h + (size_t)(k - 1) * S) + foff4; };

    k_spmvh<FH, ROWS, 0, true><<<V / ROWS, blk, 0, st>>>(
        c.rowPtr, c.colS, c.valS, x0, nullptr, slot(1), FHS);
    k_spmvh<FH, ROWS, 1, false><<<V / ROWS, blk, 0, st>>>(
        c.rowPtr, c.colS, c.valS, slot(1), x0, slot(2), FHS);
    for (int k = 3; k < 10; k++) {
        k_spmvh<FH, ROWS, 2, false><<<V / ROWS, blk, 0, st>>>(
            c.rowPtr, c.colS, c.valS, slot(k - 1), slot(k - 2), slot(k), FHS);
        if (evMid && k == 4) cudaEventRecord(evMid, st);
    }
}

extern "C" void kernel_launch(void* const* d_in, const int* in_sizes, int n_in,
                              void* d_out_v, int out_size) {
    (void)in_sizes; (void)n_in; (void)out_size;
    DevPtrs p; get_ptrs(p);
    const __half* hs = (const __half*)p.cheb;

    static cudaStream_t s0 = nullptr, s1 = nullptr;
    static cudaEvent_t evRoot, evT, evC2, evC3, evEnd;
    static cudaEvent_t evMid[5], evP1[5];
    if (!s0) {
        cudaStreamCreateWithFlags(&s0, cudaStreamNonBlocking);
        cudaStreamCreateWithFlags(&s1, cudaStreamNonBlocking);
        cudaEventCreateWithFlags(&evRoot, cudaEventDisableTiming);
        cudaEventCreateWithFlags(&evT, cudaEventDisableTiming);
        cudaEventCreateWithFlags(&evC2, cudaEventDisableTiming);
        cudaEventCreateWithFlags(&evC3, cudaEventDisableTiming);
        cudaEventCreateWithFlags(&evEnd, cudaEventDisableTiming);
        for (int i = 0; i < 5; i++) {
            cudaEventCreateWithFlags(&evMid[i], cudaEventDisableTiming);
            cudaEventCreateWithFlags(&evP1[i], cudaEventDisableTiming);
        }
    }

    const float* x    = (const float*)d_in[0];
    const float* w1_1 = (const float*)d_in[1];
    const float* b1_1 = (const float*)d_in[2];
    const float* w2_1 = (const float*)d_in[3];
    const float* b2_1 = (const float*)d_in[4];
    const int*   rows1 = (const int*)d_in[5];
    const int*   cols1 = (const int*)d_in[6];
    const float* vals1 = (const float*)d_in[7];
    const float* w1_2 = (const float*)d_in[8];
    const float* b1_2 = (const float*)d_in[9];
    const float* w2_2 = (const float*)d_in[10];
    const float* b2_2 = (const float*)d_in[11];
    const int*   rows2 = (const int*)d_in[12];
    const int*   cols2 = (const int*)d_in[13];
    const float* vals2 = (const float*)d_in[14];
    const float* w1_3 = (const float*)d_in[15];
    const float* b1_3 = (const float*)d_in[16];
    const float* w2_3 = (const float*)d_in[17];
    const float* b2_3 = (const float*)d_in[18];
    const int*   rows3 = (const int*)d_in[19];
    const int*   cols3 = (const int*)d_in[20];
    const float* vals3 = (const float*)d_in[21];

    float* d_out = (float*)d_out_v;
    float* out_skip1 = d_out;                       // [8,49152,32]
    float* out_skip2 = d_out + (size_t)12582912;    // [8,12288,64]
    float* out_skip3 = out_skip2 + (size_t)6291456; // [8,3072,128]
    float* out_x     = out_skip3 + (size_t)3145728; // [8,768,128]

    // ---- fork ----
    cudaEventRecord(evRoot, 0);
    cudaStreamWaitEvent(s0, evRoot, 0);
    cudaStreamWaitEvent(s1, evRoot, 0);

    // s1: transpose x -> b0; CSR builds for levels 2/3 hidden behind level-1
    k_transpose_in<<<divUp(V1, 256), 256, 0, s1>>>(x, p.b0, V1);
    cudaEventRecord(evT, s1);
    build_csr(p.c2, rows2, cols2, vals2, V2, E2, s1);
    cudaEventRecord(evC2, s1);
    build_csr(p.c3, rows3, cols3, vals3, V3, E3, s1);
    cudaEventRecord(evC3, s1);

    // s0: level-1 CSR, F=8 chain, conv1 GEMM (A0=b0 -> b1)
    build_csr(p.c1, rows1, cols1, vals1, V1, E1, s0);
    cudaStreamWaitEvent(s0, evT, 0);
    spmv_chainh<8, 8>(p, p.c1, p.b0, V1, 0, s0);
    k_gemm_c1<<<V1 * BATCH / 8, dim3(32, 8), 0, s0>>>(
        p.b0, hs, (size_t)V1 * 8, w1_1, b1_1, p.b1, V1 * BATCH);

    // level-1 conv2: serial half-chains (x0=b1), evMid after half-B slot 4
    spmv_chainh<128, 256>(p, p.c1, p.b1, V1, 0, s0);
    spmv_chainh<128, 256>(p, p.c1, p.b1, V1, 32, s0, evMid[0]);
    cudaStreamWaitEvent(s1, evMid[0], 0);
    k_gemm_mma<32, 32, 0><<<V1 * BATCH / 128, 256, 0, s1>>>(
        p.b1, hs, (size_t)V1 * 256, w2_1, b2_1, p.b2, nullptr, 0, 5);
    cudaEventRecord(evP1[0], s1);
    cudaStreamWaitEvent(s0, evP1[0], 0);
    k_gemm_mma<32, 32, 1><<<V1 * BATCH / 128, 256, 0, s0>>>(
        p.b1, hs, (size_t)V1 * 256, w2_1, b2_1, p.b2, p.b0, 5, 10);
    {
        int n2 = (V1 / 4) * BATCH * 8;
        k_skip_pool_next4<<<divUp(n2, 256), 256, 0, s0>>>(
            (const float4*)p.b0, (float4*)out_skip1, (float4*)p.b1, V1, 8);
    }

    // ---------------- Level 2 ----------------
    cudaStreamWaitEvent(s0, evC2, 0);
    spmv_chainh<256, 256>(p, p.c2, p.b1, V2, 0, s0, evMid[1]);
    cudaStreamWaitEvent(s1, evMid[1], 0);
    k_gemm_mma<32, 64, 0><<<V2 * BATCH / 128, 256, 0, s1>>>(
        p.b1, hs, (size_t)V2 * 256, w1_2, b1_2, p.b2, nullptr, 0, 5);
    cudaEventRecord(evP1[1], s1);
    cudaStreamWaitEvent(s0, evP1[1], 0);
    k_gemm_mma<32, 64, 1><<<V2 * BATCH / 128, 256, 0, s0>>>(
        p.b1, hs, (size_t)V2 * 256, w1_2, b1_2, p.b2, p.b0, 5, 10);

    spmv_chainh<512, 512>(p, p.c2, p.b0, V2, 0, s0, evMid[2]);
    cudaStreamWaitEvent(s1, evMid[2], 0);
    k_gemm_mma<64, 64, 0><<<V2 * BATCH / 128, 256, 0, s1>>>(
        p.b0, hs, (size_t)V2 * 512, w2_2, b2_2, p.b2, nullptr, 0, 10);
    cudaEventRecord(evP1[2], s1);
    cudaStreamWaitEvent(s0, evP1[2], 0);
    k_gemm_mma<64, 64, 1><<<V2 * BATCH / 128, 256, 0, s0>>>(
        p.b0, hs, (size_t)V2 * 512, w2_2, b2_2, p.b2, p.b1, 10, 20);
    {
        int n2 = (V2 / 4) * BATCH * 16;
        k_skip_pool_next4<<<divUp(n2, 256), 256, 0, s0>>>(
            (const float4*)p.b1, (float4*)out_skip2, (float4*)p.b0, V2, 16);
    }

    // ---------------- Level 3 ----------------
    cudaStreamWaitEvent(s0, evC3, 0);
    spmv_chainh<512, 512>(p, p.c3, p.b0, V3, 0, s0, evMid[3]);
    cudaStreamWaitEvent(s1, evMid[3], 0);
    k_gemm_mma<64, 128, 0><<<V3 * BATCH / 128, 256, 0, s1>>>(
        p.b0, hs, (size_t)V3 * 512, w1_3, b1_3, p.b2, nullptr, 0, 10);
    cudaEventRecord(evP1[3], s1);
    cudaStreamWaitEvent(s0, evP1[3], 0);
    k_gemm_mma<64, 128, 1><<<V3 * BATCH / 128, 256, 0, s0>>>(
        p.b0, hs, (size_t)V3 * 512, w1_3, b1_3, p.b2, p.b1, 10, 20);

    spmv_chainh<1024, 1024>(p, p.c3, p.b1, V3, 0, s0, evMid[4]);
    cudaStreamWaitEvent(s1, evMid[4], 0);
    k_gemm_mma<128, 128, 0><<<V3 * BATCH / 128, 256, 0, s1>>>(
        p.b1, hs, (size_t)V3 * 1024, w2_3, b2_3, p.b2, nullptr, 0, 20);
    cudaEventRecord(evP1[4], s1);
    cudaStreamWaitEvent(s0, evP1[4], 0);
    k_gemm_mma<128, 128, 1><<<V3 * BATCH / 128, 256, 0, s0>>>(
        p.b1, hs, (size_t)V3 * 1024, w2_3, b2_3, p.b2, p.b0, 20, 40);
    {
        int n2 = (V3 / 4) * BATCH * 32;
        k_skip_pool_out4<<<divUp(n2, 256), 256, 0, s0>>>(
            (const float4*)p.b0, (float4*)out_skip3, (float4*)out_x, V3, 32);
    }

    // ---- join ----
    cudaEventRecord(evEnd, s0);
    cudaStreamWaitEvent(0, evEnd, 0);
}